// round 10
// baseline (speedup 1.0000x reference)
#include <cuda_runtime.h>
#include <cuda_bf16.h>
#include <cstdint>

// Problem constants
#define BATCH 4
#define SEQ   2048
#define EMB   1024
#define NHEAD 16
#define HDIM  64
#define M_ROWS (BATCH * SEQ)      // 8192
#define QKV_N  (3 * EMB)          // 3072

// Scratch (device globals: no allocation allowed)
__device__ float g_qkv[(size_t)M_ROWS * QKV_N];   // (B*T, 3C)
__device__ float g_y[(size_t)M_ROWS * EMB];       // (B*T, C)
__device__ float g_wt_attn[(size_t)QKV_N * EMB];  // W_attn^T (3072,1024), tf32-rounded
__device__ float g_wt_proj[(size_t)EMB * EMB];    // W_proj^T (1024,1024), tf32-rounded

__device__ __forceinline__ uint32_t f2tf32(float f) {
    uint32_t r;
    asm("cvt.rna.tf32.f32 %0, %1;" : "=r"(r) : "f"(f));
    return r;
}

__device__ __forceinline__ void mma_tf32(float* c, const uint32_t* a, const uint32_t* b) {
    asm volatile(
        "mma.sync.aligned.m16n8k8.row.col.f32.tf32.tf32.f32 "
        "{%0,%1,%2,%3}, {%4,%5,%6,%7}, {%8,%9}, {%0,%1,%2,%3};"
        : "+f"(c[0]), "+f"(c[1]), "+f"(c[2]), "+f"(c[3])
        : "r"(a[0]), "r"(a[1]), "r"(a[2]), "r"(a[3]), "r"(b[0]), "r"(b[1]));
}

__device__ __forceinline__ void cpa16(void* dst_smem, const void* src) {
    uint32_t d = (uint32_t)__cvta_generic_to_shared(dst_smem);
    asm volatile("cp.async.cg.shared.global [%0], [%1], 16;" :: "r"(d), "l"(src) : "memory");
}
#define CP_COMMIT() asm volatile("cp.async.commit_group;" ::: "memory")
#define CP_WAIT2()  asm volatile("cp.async.wait_group 2;" ::: "memory")
#define CP_WAIT1()  asm volatile("cp.async.wait_group 1;" ::: "memory")
#define CP_WAIT0()  asm volatile("cp.async.wait_group 0;" ::: "memory")

// ===========================================================================
// mma.sync tf32 GEMM with 4-stage cp.async pipeline (unchanged, R9 WIN)
// ===========================================================================
#define BM 128
#define BN 128
#define BKT 16
#define ASTR 20
#define NST 4

#define GEMM_AS_FLOATS (BM * ASTR)
#define GEMM_BS_FLOATS (BN * ASTR)
#define GEMM_SMEM_FLOATS (NST * (GEMM_AS_FLOATS + GEMM_BS_FLOATS))
#define GEMM_SMEM_BYTES  (GEMM_SMEM_FLOATS * 4)

__global__ __launch_bounds__(256, 2) void gemm_mma(
    const float* __restrict__ A, const float* __restrict__ Bt,
    const float* __restrict__ bias, float* __restrict__ C,
    int N, int K)
{
    extern __shared__ __align__(16) float gsm[];
    float* Asm = gsm;
    float* Bsm = gsm + NST * GEMM_AS_FLOATS;

    const int tid  = threadIdx.x;
    const int warp = tid >> 5;
    const int lane = tid & 31;
    const int wm = warp >> 1;
    const int wn = warp & 1;
    const int g   = lane >> 2;
    const int tig = lane & 3;
    const int m0 = blockIdx.y * BM;
    const int n0 = blockIdx.x * BN;

    const int ch0 = tid * 2;
    const int lr0 = ch0 >> 2;
    const int lk0 = (ch0 & 3) * 4;
    const int lr1 = (ch0 + 1) >> 2;
    const int lk1 = ((ch0 + 1) & 3) * 4;

    const float* Abase = A  + (size_t)m0 * K;
    const float* Bbase = Bt + (size_t)n0 * K;

    float acc[2][8][4];
    #pragma unroll
    for (int i = 0; i < 2; i++)
        #pragma unroll
        for (int j = 0; j < 8; j++)
            #pragma unroll
            for (int r = 0; r < 4; r++) acc[i][j][r] = 0.f;

    const int niter = K / BKT;

    #pragma unroll
    for (int s = 0; s < NST - 1; s++) {
        const int k0 = s * BKT;
        cpa16(&Asm[s * GEMM_AS_FLOATS + lr0 * ASTR + lk0], Abase + (size_t)lr0 * K + k0 + lk0);
        cpa16(&Asm[s * GEMM_AS_FLOATS + lr1 * ASTR + lk1], Abase + (size_t)lr1 * K + k0 + lk1);
        cpa16(&Bsm[s * GEMM_BS_FLOATS + lr0 * ASTR + lk0], Bbase + (size_t)lr0 * K + k0 + lk0);
        cpa16(&Bsm[s * GEMM_BS_FLOATS + lr1 * ASTR + lk1], Bbase + (size_t)lr1 * K + k0 + lk1);
        CP_COMMIT();
    }

    for (int it = 0; it < niter; it++) {
        const int st = it & (NST - 1);
        const float* As = Asm + st * GEMM_AS_FLOATS;
        const float* Bs = Bsm + st * GEMM_BS_FLOATS;

        CP_WAIT2();
        __syncthreads();

        const int pre = it + NST - 1;
        if (pre < niter) {
            const int ps = pre & (NST - 1);
            const int k0 = pre * BKT;
            cpa16(&Asm[ps * GEMM_AS_FLOATS + lr0 * ASTR + lk0], Abase + (size_t)lr0 * K + k0 + lk0);
            cpa16(&Asm[ps * GEMM_AS_FLOATS + lr1 * ASTR + lk1], Abase + (size_t)lr1 * K + k0 + lk1);
            cpa16(&Bsm[ps * GEMM_BS_FLOATS + lr0 * ASTR + lk0], Bbase + (size_t)lr0 * K + k0 + lk0);
            cpa16(&Bsm[ps * GEMM_BS_FLOATS + lr1 * ASTR + lk1], Bbase + (size_t)lr1 * K + k0 + lk1);
        }
        CP_COMMIT();

        #pragma unroll
        for (int ks = 0; ks < 2; ks++) {
            const int kb = ks * 8;
            uint32_t af[2][4], bf[8][2];
            #pragma unroll
            for (int mf = 0; mf < 2; mf++) {
                const int base = (wm * 32 + mf * 16 + g) * ASTR + kb + tig;
                af[mf][0] = f2tf32(As[base]);
                af[mf][1] = f2tf32(As[base + 8 * ASTR]);
                af[mf][2] = f2tf32(As[base + 4]);
                af[mf][3] = f2tf32(As[base + 8 * ASTR + 4]);
            }
            #pragma unroll
            for (int nf = 0; nf < 8; nf++) {
                const int base = (wn * 64 + nf * 8 + g) * ASTR + kb + tig;
                bf[nf][0] = __float_as_uint(Bs[base]);
                bf[nf][1] = __float_as_uint(Bs[base + 4]);
            }
            #pragma unroll
            for (int mf = 0; mf < 2; mf++)
                #pragma unroll
                for (int nf = 0; nf < 8; nf++)
                    mma_tf32(acc[mf][nf], af[mf], bf[nf]);
        }
    }

    #pragma unroll
    for (int mf = 0; mf < 2; mf++) {
        const int row = m0 + wm * 32 + mf * 16 + g;
        #pragma unroll
        for (int nf = 0; nf < 8; nf++) {
            const int col = n0 + wn * 64 + nf * 8 + tig * 2;
            const float b0 = __ldg(bias + col);
            const float b1 = __ldg(bias + col + 1);
            float2 v0 = { acc[mf][nf][0] + b0, acc[mf][nf][1] + b1 };
            float2 v1 = { acc[mf][nf][2] + b0, acc[mf][nf][3] + b1 };
            *(float2*)(C + (size_t)row * N + col)       = v0;
            *(float2*)(C + (size_t)(row + 8) * N + col) = v1;
        }
    }
}

// ===========================================================================
// transpose + tf32 round (unchanged)
// ===========================================================================
__global__ __launch_bounds__(256) void transpose_k(
    const float* __restrict__ in, float* __restrict__ out, int R, int C)
{
    __shared__ float t[32][33];
    const int bx = blockIdx.x * 32;
    const int by = blockIdx.y * 32;
    #pragma unroll
    for (int j = 0; j < 32; j += 8) {
        int r = by + threadIdx.y + j;
        t[threadIdx.y + j][threadIdx.x] = in[(size_t)r * C + bx + threadIdx.x];
    }
    __syncthreads();
    #pragma unroll
    for (int j = 0; j < 32; j += 8) {
        int c = bx + threadIdx.y + j;
        out[(size_t)c * R + by + threadIdx.x] =
            __uint_as_float(f2tf32(t[threadIdx.x][threadIdx.y + j]));
    }
}

// ===========================================================================
// Tensor-core flash attention v2 (causal), mma.sync tf32.
// NEW vs R5: cp.async double-buffered RAW K/V tiles; hi/lo split + tf32
// rounding moved to fragment-load time (bit-identical values, LDS halved,
// synchronous load phase removed from critical path).
// ===========================================================================
#define QT 64
#define KT 64
#define KSTR 68
#define VSTR 72
#define PSTR 68

// smem layout (floats): raw K (2 stages), raw V (2 stages), P
#define S_K0  0
#define S_K1  (S_K0 + KT * KSTR)                 // 4352
#define S_V0  (S_K1 + KT * KSTR)                 // 8704
#define S_V1  (S_V0 + KT * VSTR)                 // 13312
#define S_P   (S_V1 + KT * VSTR)                 // 17920
#define FLASH_SMEM_FLOATS (S_P + 4 * 16 * PSTR)  // 22272
#define FLASH_SMEM_BYTES  (FLASH_SMEM_FLOATS * 4) // 89088

__global__ __launch_bounds__(128) void flash_mma(
    const float* __restrict__ qkv, float* __restrict__ Y)
{
    extern __shared__ __align__(16) float sm[];
    uint32_t* smu = (uint32_t*)sm;

    const int b  = blockIdx.z;
    const int h  = blockIdx.y;
    const int qt = gridDim.x - 1 - blockIdx.x;   // heavy blocks first
    const int qb = qt * QT;
    const int tid  = threadIdx.x;
    const int w    = tid >> 5;
    const int lane = tid & 31;
    const int g    = lane >> 2;
    const int tig  = lane & 3;

    const float* base = qkv + (size_t)b * SEQ * QKV_N;

    // loader mapping for cp.async: 16 chunks of 16B per thread per tile (8 K + 8 V)
    const int lrow = tid >> 4;            // 0..7  (row group base)
    const int lcol = (tid & 15) * 4;      // 0..60 (float offset)

    // issue one K/V tile's cp.asyncs into stage st
    auto issue_tile = [&](int k0, int st) {
        float* Ks = sm + (st ? S_K1 : S_K0);
        float* Vs = sm + (st ? S_V1 : S_V0);
        #pragma unroll
        for (int i = 0; i < 8; i++) {
            const int r = lrow + i * 8;
            const float* krow = base + (size_t)(k0 + r) * QKV_N + EMB + h * HDIM + lcol;
            cpa16(&Ks[r * KSTR + lcol], krow);
            cpa16(&Vs[r * VSTR + lcol], krow + EMB);
        }
        CP_COMMIT();
    };

    // ---- Q fragments (scaled by 1/8 exactly, split hi/lo) ----
    uint32_t qhi[8][4], qlo[8][4];
    {
        const float* qlorow = base + (size_t)(qb + w * 16 + g) * QKV_N + h * HDIM;
        const float* qhirow = qlorow + 8 * QKV_N;
        #pragma unroll
        for (int kk = 0; kk < 8; kk++) {
            float v0 = qlorow[kk * 8 + tig]     * 0.125f;
            float v1 = qhirow[kk * 8 + tig]     * 0.125f;
            float v2 = qlorow[kk * 8 + tig + 4] * 0.125f;
            float v3 = qhirow[kk * 8 + tig + 4] * 0.125f;
            float h0 = __uint_as_float(__float_as_uint(v0) & 0xffffe000u);
            float h1 = __uint_as_float(__float_as_uint(v1) & 0xffffe000u);
            float h2 = __uint_as_float(__float_as_uint(v2) & 0xffffe000u);
            float h3 = __uint_as_float(__float_as_uint(v3) & 0xffffe000u);
            qhi[kk][0] = __float_as_uint(h0);
            qhi[kk][1] = __float_as_uint(h1);
            qhi[kk][2] = __float_as_uint(h2);
            qhi[kk][3] = __float_as_uint(h3);
            qlo[kk][0] = f2tf32(v0 - h0);
            qlo[kk][1] = f2tf32(v1 - h1);
            qlo[kk][2] = f2tf32(v2 - h2);
            qlo[kk][3] = f2tf32(v3 - h3);
        }
    }

    // prologue: issue tile 0 into stage 0
    issue_tile(0, 0);

    float o[8][4];
    #pragma unroll
    for (int nt = 0; nt < 8; nt++)
        #pragma unroll
        for (int r = 0; r < 4; r++) o[nt][r] = 0.f;
    float m_lo = -1e30f, m_hi = -1e30f;
    float l_lo = 0.f,    l_hi = 0.f;

    uint32_t* Pw = smu + S_P + w * 16 * PSTR;

    for (int kt = 0; kt <= qt; kt++) {
        const int st = kt & 1;
        const uint32_t* Ks = smu + (st ? S_K1 : S_K0);
        const uint32_t* Vs = smu + (st ? S_V1 : S_V0);

        // issue next tile into the other stage, then wait for current tile
        if (kt < qt) {
            issue_tile((kt + 1) * KT, st ^ 1);
            CP_WAIT1();
        } else {
            CP_WAIT0();
        }
        __syncthreads();   // current stage visible to all; prev reads done before this issue

        // ---- S = Q.K^T (3xTF32), K hi/lo derived from raw smem ----
        float s[8][4];
        #pragma unroll
        for (int nt = 0; nt < 8; nt++)
            #pragma unroll
            for (int r = 0; r < 4; r++) s[nt][r] = 0.f;

        #pragma unroll
        for (int kk = 0; kk < 8; kk++) {
            #pragma unroll
            for (int nt = 0; nt < 8; nt++) {
                const int ra = nt * 8 + g;
                const uint32_t raw0 = Ks[ra * KSTR + kk * 8 + tig];
                const uint32_t raw1 = Ks[ra * KSTR + kk * 8 + tig + 4];
                uint32_t bh[2], bl[2];
                bh[0] = raw0 & 0xffffe000u;
                bh[1] = raw1 & 0xffffe000u;
                bl[0] = f2tf32(__uint_as_float(raw0) - __uint_as_float(bh[0]));
                bl[1] = f2tf32(__uint_as_float(raw1) - __uint_as_float(bh[1]));
                mma_tf32(s[nt], qhi[kk], bh);
                mma_tf32(s[nt], qhi[kk], bl);
                mma_tf32(s[nt], qlo[kk], bh);
            }
        }

        // ---- causal mask (diagonal tile only) ----
        if (kt == qt) {
            const int rlo = w * 16 + g;
            const int rhi = rlo + 8;
            #pragma unroll
            for (int nt = 0; nt < 8; nt++) {
                const int c0 = nt * 8 + 2 * tig;
                if (c0     > rlo) s[nt][0] = -1e30f;
                if (c0 + 1 > rlo) s[nt][1] = -1e30f;
                if (c0     > rhi) s[nt][2] = -1e30f;
                if (c0 + 1 > rhi) s[nt][3] = -1e30f;
            }
        }

        // ---- online softmax ----
        float mx_lo = -1e30f, mx_hi = -1e30f;
        #pragma unroll
        for (int nt = 0; nt < 8; nt++) {
            mx_lo = fmaxf(mx_lo, fmaxf(s[nt][0], s[nt][1]));
            mx_hi = fmaxf(mx_hi, fmaxf(s[nt][2], s[nt][3]));
        }
        mx_lo = fmaxf(mx_lo, __shfl_xor_sync(0xffffffffu, mx_lo, 1));
        mx_lo = fmaxf(mx_lo, __shfl_xor_sync(0xffffffffu, mx_lo, 2));
        mx_hi = fmaxf(mx_hi, __shfl_xor_sync(0xffffffffu, mx_hi, 1));
        mx_hi = fmaxf(mx_hi, __shfl_xor_sync(0xffffffffu, mx_hi, 2));

        const float mn_lo = fmaxf(m_lo, mx_lo);
        const float mn_hi = fmaxf(m_hi, mx_hi);
        const float cr_lo = __expf(m_lo - mn_lo);
        const float cr_hi = __expf(m_hi - mn_hi);
        m_lo = mn_lo; m_hi = mn_hi;
        l_lo *= cr_lo; l_hi *= cr_hi;
        #pragma unroll
        for (int nt = 0; nt < 8; nt++) {
            o[nt][0] *= cr_lo;
            o[nt][1] *= cr_lo;
            o[nt][2] *= cr_hi;
            o[nt][3] *= cr_hi;
        }

        // ---- P = exp(s - m), accumulate l, stage P to smem ----
        #pragma unroll
        for (int nt = 0; nt < 8; nt++) {
            float p0 = __expf(s[nt][0] - mn_lo);
            float p1 = __expf(s[nt][1] - mn_lo);
            float p2 = __expf(s[nt][2] - mn_hi);
            float p3 = __expf(s[nt][3] - mn_hi);
            l_lo += p0 + p1;
            l_hi += p2 + p3;
            uint32_t* Plo = Pw + g * PSTR + nt * 8 + 2 * tig;
            uint32_t* Phi = Pw + (g + 8) * PSTR + nt * 8 + 2 * tig;
            Plo[0] = f2tf32(p0);
            Plo[1] = f2tf32(p1);
            Phi[0] = f2tf32(p2);
            Phi[1] = f2tf32(p3);
        }
        __syncwarp();

        // ---- O += P.V (V rounded rna at fragment load) ----
        #pragma unroll
        for (int kk = 0; kk < 8; kk++) {
            uint32_t pa[4];
            pa[0] = Pw[g * PSTR + kk * 8 + tig];
            pa[1] = Pw[(g + 8) * PSTR + kk * 8 + tig];
            pa[2] = Pw[g * PSTR + kk * 8 + tig + 4];
            pa[3] = Pw[(g + 8) * PSTR + kk * 8 + tig + 4];
            #pragma unroll
            for (int nt = 0; nt < 8; nt++) {
                uint32_t vb[2];
                vb[0] = f2tf32(__uint_as_float(Vs[(kk * 8 + tig) * VSTR + nt * 8 + g]));
                vb[1] = f2tf32(__uint_as_float(Vs[(kk * 8 + tig + 4) * VSTR + nt * 8 + g]));
                mma_tf32(o[nt], pa, vb);
            }
        }
        __syncthreads();   // all reads of current stage done before it is re-issued
    }

    // ---- finalize: full row sums, normalize, write ----
    l_lo += __shfl_xor_sync(0xffffffffu, l_lo, 1);
    l_lo += __shfl_xor_sync(0xffffffffu, l_lo, 2);
    l_hi += __shfl_xor_sync(0xffffffffu, l_hi, 1);
    l_hi += __shfl_xor_sync(0xffffffffu, l_hi, 2);
    const float inv_lo = 1.f / l_lo;
    const float inv_hi = 1.f / l_hi;

    const int row_lo = qb + w * 16 + g;
    float* ylo = Y + (size_t)(b * SEQ + row_lo) * EMB + h * HDIM;
    float* yhi = ylo + 8 * EMB;
    #pragma unroll
    for (int nt = 0; nt < 8; nt++) {
        const int col = nt * 8 + 2 * tig;
        float2 v0 = { o[nt][0] * inv_lo, o[nt][1] * inv_lo };
        float2 v1 = { o[nt][2] * inv_hi, o[nt][3] * inv_hi };
        *(float2*)(ylo + col) = v0;
        *(float2*)(yhi + col) = v1;
    }
}

// ===========================================================================
// kernel_launch
// ===========================================================================
extern "C" void kernel_launch(void* const* d_in, const int* in_sizes, int n_in,
                              void* d_out, int out_size)
{
    const float* x      = (const float*)d_in[0];
    const float* W_attn = (const float*)d_in[1];
    const float* b_attn = (const float*)d_in[2];
    const float* W_proj = (const float*)d_in[3];
    const float* b_proj = (const float*)d_in[4];
    float* out = (float*)d_out;

    float *qkv, *y, *wt_attn, *wt_proj;
    cudaGetSymbolAddress((void**)&qkv, g_qkv);
    cudaGetSymbolAddress((void**)&y, g_y);
    cudaGetSymbolAddress((void**)&wt_attn, g_wt_attn);
    cudaGetSymbolAddress((void**)&wt_proj, g_wt_proj);

    static bool attr_set = false;
    if (!attr_set) {
        cudaFuncSetAttribute(flash_mma, cudaFuncAttributeMaxDynamicSharedMemorySize,
                             FLASH_SMEM_BYTES);
        cudaFuncSetAttribute(gemm_mma, cudaFuncAttributeMaxDynamicSharedMemorySize,
                             GEMM_SMEM_BYTES);
        attr_set = true;
    }

    // 0) transpose weights to K-major (N, K), tf32-rounded
    {
        dim3 bdim(32, 8);
        transpose_k<<<dim3(QKV_N / 32, EMB / 32), bdim>>>(W_attn, wt_attn, EMB, QKV_N);
        transpose_k<<<dim3(EMB / 32, EMB / 32), bdim>>>(W_proj, wt_proj, EMB, EMB);
    }

    // 1) QKV projection (mma.sync tf32, cp.async pipeline)
    {
        dim3 grid(QKV_N / BN, M_ROWS / BM);
        gemm_mma<<<grid, 256, GEMM_SMEM_BYTES>>>(x, wt_attn, b_attn, qkv, QKV_N, EMB);
    }

    // 2) causal flash attention (mma.sync tf32, 3xTF32 QK, cp.async K/V)
    {
        dim3 grid(SEQ / QT, NHEAD, BATCH);
        flash_mma<<<grid, 128, FLASH_SMEM_BYTES>>>(qkv, y);
    }

    // 3) output projection (mma.sync tf32, cp.async pipeline)
    {
        dim3 grid(EMB / BN, M_ROWS / BM);
        gemm_mma<<<grid, 256, GEMM_SMEM_BYTES>>>(y, wt_proj, b_proj, out, EMB, EMB);
    }
}

// round 13
// speedup vs baseline: 1.1110x; 1.1110x over previous
#include <cuda_runtime.h>
#include <cuda_bf16.h>
#include <cstdint>

// Problem constants
#define BATCH 4
#define SEQ   2048
#define EMB   1024
#define NHEAD 16
#define HDIM  64
#define M_ROWS (BATCH * SEQ)      // 8192
#define QKV_N  (3 * EMB)          // 3072

// Scratch (device globals: no allocation allowed)
__device__ float g_qkv[(size_t)M_ROWS * QKV_N];   // (B*T, 3C)
__device__ float g_y[(size_t)M_ROWS * EMB];       // (B*T, C)
__device__ float g_wt_attn[(size_t)QKV_N * EMB];  // W_attn^T (3072,1024), tf32-rounded
__device__ float g_wt_proj[(size_t)EMB * EMB];    // W_proj^T (1024,1024), tf32-rounded

__device__ __forceinline__ uint32_t f2tf32(float f) {
    uint32_t r;
    asm("cvt.rna.tf32.f32 %0, %1;" : "=r"(r) : "f"(f));
    return r;
}

__device__ __forceinline__ void mma_tf32(float* c, const uint32_t* a, const uint32_t* b) {
    asm volatile(
        "mma.sync.aligned.m16n8k8.row.col.f32.tf32.tf32.f32 "
        "{%0,%1,%2,%3}, {%4,%5,%6,%7}, {%8,%9}, {%0,%1,%2,%3};"
        : "+f"(c[0]), "+f"(c[1]), "+f"(c[2]), "+f"(c[3])
        : "r"(a[0]), "r"(a[1]), "r"(a[2]), "r"(a[3]), "r"(b[0]), "r"(b[1]));
}

__device__ __forceinline__ void cpa16(void* dst_smem, const void* src) {
    uint32_t d = (uint32_t)__cvta_generic_to_shared(dst_smem);
    asm volatile("cp.async.cg.shared.global [%0], [%1], 16;" :: "r"(d), "l"(src) : "memory");
}
#define CP_COMMIT() asm volatile("cp.async.commit_group;" ::: "memory")
#define CP_WAIT2()  asm volatile("cp.async.wait_group 2;" ::: "memory")
#define CP_WAIT1()  asm volatile("cp.async.wait_group 1;" ::: "memory")
#define CP_WAIT0()  asm volatile("cp.async.wait_group 0;" ::: "memory")

// ===========================================================================
// mma.sync tf32 GEMM with 4-stage cp.async pipeline (unchanged, R9 WIN)
// ===========================================================================
#define BM 128
#define BN 128
#define BKT 16
#define ASTR 20
#define NST 4

#define GEMM_AS_FLOATS (BM * ASTR)
#define GEMM_BS_FLOATS (BN * ASTR)
#define GEMM_SMEM_FLOATS (NST * (GEMM_AS_FLOATS + GEMM_BS_FLOATS))
#define GEMM_SMEM_BYTES  (GEMM_SMEM_FLOATS * 4)

__global__ __launch_bounds__(256, 2) void gemm_mma(
    const float* __restrict__ A, const float* __restrict__ Bt,
    const float* __restrict__ bias, float* __restrict__ C,
    int N, int K)
{
    extern __shared__ __align__(16) float gsm[];
    float* Asm = gsm;
    float* Bsm = gsm + NST * GEMM_AS_FLOATS;

    const int tid  = threadIdx.x;
    const int warp = tid >> 5;
    const int lane = tid & 31;
    const int wm = warp >> 1;
    const int wn = warp & 1;
    const int g   = lane >> 2;
    const int tig = lane & 3;
    const int m0 = blockIdx.y * BM;
    const int n0 = blockIdx.x * BN;

    const int ch0 = tid * 2;
    const int lr0 = ch0 >> 2;
    const int lk0 = (ch0 & 3) * 4;
    const int lr1 = (ch0 + 1) >> 2;
    const int lk1 = ((ch0 + 1) & 3) * 4;

    const float* Abase = A  + (size_t)m0 * K;
    const float* Bbase = Bt + (size_t)n0 * K;

    float acc[2][8][4];
    #pragma unroll
    for (int i = 0; i < 2; i++)
        #pragma unroll
        for (int j = 0; j < 8; j++)
            #pragma unroll
            for (int r = 0; r < 4; r++) acc[i][j][r] = 0.f;

    const int niter = K / BKT;

    #pragma unroll
    for (int s = 0; s < NST - 1; s++) {
        const int k0 = s * BKT;
        cpa16(&Asm[s * GEMM_AS_FLOATS + lr0 * ASTR + lk0], Abase + (size_t)lr0 * K + k0 + lk0);
        cpa16(&Asm[s * GEMM_AS_FLOATS + lr1 * ASTR + lk1], Abase + (size_t)lr1 * K + k0 + lk1);
        cpa16(&Bsm[s * GEMM_BS_FLOATS + lr0 * ASTR + lk0], Bbase + (size_t)lr0 * K + k0 + lk0);
        cpa16(&Bsm[s * GEMM_BS_FLOATS + lr1 * ASTR + lk1], Bbase + (size_t)lr1 * K + k0 + lk1);
        CP_COMMIT();
    }

    for (int it = 0; it < niter; it++) {
        const int st = it & (NST - 1);
        const float* As = Asm + st * GEMM_AS_FLOATS;
        const float* Bs = Bsm + st * GEMM_BS_FLOATS;

        CP_WAIT2();
        __syncthreads();

        const int pre = it + NST - 1;
        if (pre < niter) {
            const int ps = pre & (NST - 1);
            const int k0 = pre * BKT;
            cpa16(&Asm[ps * GEMM_AS_FLOATS + lr0 * ASTR + lk0], Abase + (size_t)lr0 * K + k0 + lk0);
            cpa16(&Asm[ps * GEMM_AS_FLOATS + lr1 * ASTR + lk1], Abase + (size_t)lr1 * K + k0 + lk1);
            cpa16(&Bsm[ps * GEMM_BS_FLOATS + lr0 * ASTR + lk0], Bbase + (size_t)lr0 * K + k0 + lk0);
            cpa16(&Bsm[ps * GEMM_BS_FLOATS + lr1 * ASTR + lk1], Bbase + (size_t)lr1 * K + k0 + lk1);
        }
        CP_COMMIT();

        #pragma unroll
        for (int ks = 0; ks < 2; ks++) {
            const int kb = ks * 8;
            uint32_t af[2][4], bf[8][2];
            #pragma unroll
            for (int mf = 0; mf < 2; mf++) {
                const int base = (wm * 32 + mf * 16 + g) * ASTR + kb + tig;
                af[mf][0] = f2tf32(As[base]);
                af[mf][1] = f2tf32(As[base + 8 * ASTR]);
                af[mf][2] = f2tf32(As[base + 4]);
                af[mf][3] = f2tf32(As[base + 8 * ASTR + 4]);
            }
            #pragma unroll
            for (int nf = 0; nf < 8; nf++) {
                const int base = (wn * 64 + nf * 8 + g) * ASTR + kb + tig;
                bf[nf][0] = __float_as_uint(Bs[base]);
                bf[nf][1] = __float_as_uint(Bs[base + 4]);
            }
            #pragma unroll
            for (int mf = 0; mf < 2; mf++)
                #pragma unroll
                for (int nf = 0; nf < 8; nf++)
                    mma_tf32(acc[mf][nf], af[mf], bf[nf]);
        }
    }

    #pragma unroll
    for (int mf = 0; mf < 2; mf++) {
        const int row = m0 + wm * 32 + mf * 16 + g;
        #pragma unroll
        for (int nf = 0; nf < 8; nf++) {
            const int col = n0 + wn * 64 + nf * 8 + tig * 2;
            const float b0 = __ldg(bias + col);
            const float b1 = __ldg(bias + col + 1);
            float2 v0 = { acc[mf][nf][0] + b0, acc[mf][nf][1] + b1 };
            float2 v1 = { acc[mf][nf][2] + b0, acc[mf][nf][3] + b1 };
            *(float2*)(C + (size_t)row * N + col)       = v0;
            *(float2*)(C + (size_t)(row + 8) * N + col) = v1;
        }
    }
}

// ===========================================================================
// transpose + tf32 round (unchanged)
// ===========================================================================
__global__ __launch_bounds__(256) void transpose_k(
    const float* __restrict__ in, float* __restrict__ out, int R, int C)
{
    __shared__ float t[32][33];
    const int bx = blockIdx.x * 32;
    const int by = blockIdx.y * 32;
    #pragma unroll
    for (int j = 0; j < 32; j += 8) {
        int r = by + threadIdx.y + j;
        t[threadIdx.y + j][threadIdx.x] = in[(size_t)r * C + bx + threadIdx.x];
    }
    __syncthreads();
    #pragma unroll
    for (int j = 0; j < 32; j += 8) {
        int c = bx + threadIdx.y + j;
        out[(size_t)c * R + by + threadIdx.x] =
            __uint_as_float(f2tf32(t[threadIdx.x][threadIdx.y + j]));
    }
}

// ===========================================================================
// Tensor-core flash attention v3 (causal), mma.sync tf32.
// vs R10: QK is 2xTF32 (exact Q split x single-rounded K) -> 25% less tensor
// work, no per-fragment K split; V single-buffered -> 69KB smem -> 3 CTAs/SM.
// K double-buffered via cp.async; V(kt) issued at top of iter kt, consumed
// after QK+softmax (latency hidden by compute).
// ===========================================================================
#define QT 64
#define KT 64
#define KSTR 68
#define VSTR 72
#define PSTR 68

// smem layout (floats): raw K (2 stages), raw V (1 stage), P
#define S_K0  0
#define S_K1  (S_K0 + KT * KSTR)                 // 4352
#define S_V   (S_K1 + KT * KSTR)                 // 8704
#define S_P   (S_V + KT * VSTR)                  // 13312
#define FLASH_SMEM_FLOATS (S_P + 4 * 16 * PSTR)  // 17664
#define FLASH_SMEM_BYTES  (FLASH_SMEM_FLOATS * 4) // 70656

__global__ __launch_bounds__(128, 3) void flash_mma(
    const float* __restrict__ qkv, float* __restrict__ Y)
{
    extern __shared__ __align__(16) float sm[];
    uint32_t* smu = (uint32_t*)sm;

    const int b  = blockIdx.z;
    const int h  = blockIdx.y;
    const int qt = gridDim.x - 1 - blockIdx.x;   // heavy blocks first
    const int qb = qt * QT;
    const int tid  = threadIdx.x;
    const int w    = tid >> 5;
    const int lane = tid & 31;
    const int g    = lane >> 2;
    const int tig  = lane & 3;

    const float* base = qkv + (size_t)b * SEQ * QKV_N;

    // loader mapping for cp.async: 8 chunks of 16B per thread per tile
    const int lrow = tid >> 4;            // 0..7  (row group base)
    const int lcol = (tid & 15) * 4;      // 0..60 (float offset)

    // issue K tile cp.asyncs into stage st (own commit group)
    auto issue_K = [&](int k0, int st) {
        float* Ks = sm + (st ? S_K1 : S_K0);
        #pragma unroll
        for (int i = 0; i < 8; i++) {
            const int r = lrow + i * 8;
            cpa16(&Ks[r * KSTR + lcol],
                  base + (size_t)(k0 + r) * QKV_N + EMB + h * HDIM + lcol);
        }
        CP_COMMIT();
    };
    // issue V tile cp.asyncs into the single V buffer (own commit group)
    auto issue_V = [&](int k0) {
        float* Vs = sm + S_V;
        #pragma unroll
        for (int i = 0; i < 8; i++) {
            const int r = lrow + i * 8;
            cpa16(&Vs[r * VSTR + lcol],
                  base + (size_t)(k0 + r) * QKV_N + 2 * EMB + h * HDIM + lcol);
        }
        CP_COMMIT();
    };

    // ---- Q fragments (scaled by 1/8 exactly, split hi/lo; split is exact) ----
    uint32_t qhi[8][4], qlo[8][4];
    {
        const float* qlorow = base + (size_t)(qb + w * 16 + g) * QKV_N + h * HDIM;
        const float* qhirow = qlorow + 8 * QKV_N;
        #pragma unroll
        for (int kk = 0; kk < 8; kk++) {
            float v0 = qlorow[kk * 8 + tig]     * 0.125f;
            float v1 = qhirow[kk * 8 + tig]     * 0.125f;
            float v2 = qlorow[kk * 8 + tig + 4] * 0.125f;
            float v3 = qhirow[kk * 8 + tig + 4] * 0.125f;
            float h0 = __uint_as_float(__float_as_uint(v0) & 0xffffe000u);
            float h1 = __uint_as_float(__float_as_uint(v1) & 0xffffe000u);
            float h2 = __uint_as_float(__float_as_uint(v2) & 0xffffe000u);
            float h3 = __uint_as_float(__float_as_uint(v3) & 0xffffe000u);
            qhi[kk][0] = __float_as_uint(h0);
            qhi[kk][1] = __float_as_uint(h1);
            qhi[kk][2] = __float_as_uint(h2);
            qhi[kk][3] = __float_as_uint(h3);
            qlo[kk][0] = f2tf32(v0 - h0);
            qlo[kk][1] = f2tf32(v1 - h1);
            qlo[kk][2] = f2tf32(v2 - h2);
            qlo[kk][3] = f2tf32(v3 - h3);
        }
    }

    // prologue: K(0) into stage 0
    issue_K(0, 0);

    float o[8][4];
    #pragma unroll
    for (int nt = 0; nt < 8; nt++)
        #pragma unroll
        for (int r = 0; r < 4; r++) o[nt][r] = 0.f;
    float m_lo = -1e30f, m_hi = -1e30f;
    float l_lo = 0.f,    l_hi = 0.f;

    uint32_t* Pw = smu + S_P + w * 16 * PSTR;

    for (int kt = 0; kt <= qt; kt++) {
        const int st = kt & 1;
        const uint32_t* Ks = smu + (st ? S_K1 : S_K0);
        const uint32_t* Vs = smu + S_V;

        // issue V(kt), then K(kt+1); wait so that K(kt) and V(kt) are complete
        issue_V(kt * KT);
        if (kt < qt) {
            issue_K((kt + 1) * KT, st ^ 1);
            CP_WAIT1();              // only K(kt+1) may remain outstanding
        } else {
            CP_WAIT0();
        }
        __syncthreads();

        // ---- S = Q.K^T (2xTF32: exact-Q x rna-K) ----
        float s[8][4];
        #pragma unroll
        for (int nt = 0; nt < 8; nt++)
            #pragma unroll
            for (int r = 0; r < 4; r++) s[nt][r] = 0.f;

        #pragma unroll
        for (int kk = 0; kk < 8; kk++) {
            #pragma unroll
            for (int nt = 0; nt < 8; nt++) {
                const int ra = nt * 8 + g;
                uint32_t kr[2];
                kr[0] = f2tf32(__uint_as_float(Ks[ra * KSTR + kk * 8 + tig]));
                kr[1] = f2tf32(__uint_as_float(Ks[ra * KSTR + kk * 8 + tig + 4]));
                mma_tf32(s[nt], qhi[kk], kr);
                mma_tf32(s[nt], qlo[kk], kr);
            }
        }

        // ---- causal mask (diagonal tile only) ----
        if (kt == qt) {
            const int rlo = w * 16 + g;
            const int rhi = rlo + 8;
            #pragma unroll
            for (int nt = 0; nt < 8; nt++) {
                const int c0 = nt * 8 + 2 * tig;
                if (c0     > rlo) s[nt][0] = -1e30f;
                if (c0 + 1 > rlo) s[nt][1] = -1e30f;
                if (c0     > rhi) s[nt][2] = -1e30f;
                if (c0 + 1 > rhi) s[nt][3] = -1e30f;
            }
        }

        // ---- online softmax ----
        float mx_lo = -1e30f, mx_hi = -1e30f;
        #pragma unroll
        for (int nt = 0; nt < 8; nt++) {
            mx_lo = fmaxf(mx_lo, fmaxf(s[nt][0], s[nt][1]));
            mx_hi = fmaxf(mx_hi, fmaxf(s[nt][2], s[nt][3]));
        }
        mx_lo = fmaxf(mx_lo, __shfl_xor_sync(0xffffffffu, mx_lo, 1));
        mx_lo = fmaxf(mx_lo, __shfl_xor_sync(0xffffffffu, mx_lo, 2));
        mx_hi = fmaxf(mx_hi, __shfl_xor_sync(0xffffffffu, mx_hi, 1));
        mx_hi = fmaxf(mx_hi, __shfl_xor_sync(0xffffffffu, mx_hi, 2));

        const float mn_lo = fmaxf(m_lo, mx_lo);
        const float mn_hi = fmaxf(m_hi, mx_hi);
        const float cr_lo = __expf(m_lo - mn_lo);
        const float cr_hi = __expf(m_hi - mn_hi);
        m_lo = mn_lo; m_hi = mn_hi;
        l_lo *= cr_lo; l_hi *= cr_hi;
        #pragma unroll
        for (int nt = 0; nt < 8; nt++) {
            o[nt][0] *= cr_lo;
            o[nt][1] *= cr_lo;
            o[nt][2] *= cr_hi;
            o[nt][3] *= cr_hi;
        }

        // ---- P = exp(s - m), accumulate l, stage P to smem ----
        #pragma unroll
        for (int nt = 0; nt < 8; nt++) {
            float p0 = __expf(s[nt][0] - mn_lo);
            float p1 = __expf(s[nt][1] - mn_lo);
            float p2 = __expf(s[nt][2] - mn_hi);
            float p3 = __expf(s[nt][3] - mn_hi);
            l_lo += p0 + p1;
            l_hi += p2 + p3;
            uint32_t* Plo = Pw + g * PSTR + nt * 8 + 2 * tig;
            uint32_t* Phi = Pw + (g + 8) * PSTR + nt * 8 + 2 * tig;
            Plo[0] = f2tf32(p0);
            Plo[1] = f2tf32(p1);
            Phi[0] = f2tf32(p2);
            Phi[1] = f2tf32(p3);
        }
        __syncwarp();

        // ---- O += P.V (V rounded rna at fragment load) ----
        #pragma unroll
        for (int kk = 0; kk < 8; kk++) {
            uint32_t pa[4];
            pa[0] = Pw[g * PSTR + kk * 8 + tig];
            pa[1] = Pw[(g + 8) * PSTR + kk * 8 + tig];
            pa[2] = Pw[g * PSTR + kk * 8 + tig + 4];
            pa[3] = Pw[(g + 8) * PSTR + kk * 8 + tig + 4];
            #pragma unroll
            for (int nt = 0; nt < 8; nt++) {
                uint32_t vb[2];
                vb[0] = f2tf32(__uint_as_float(Vs[(kk * 8 + tig) * VSTR + nt * 8 + g]));
                vb[1] = f2tf32(__uint_as_float(Vs[(kk * 8 + tig + 4) * VSTR + nt * 8 + g]));
                mma_tf32(o[nt], pa, vb);
            }
        }
        __syncthreads();   // all reads of V and K stage st done before reuse
    }

    // ---- finalize: full row sums, normalize, write ----
    l_lo += __shfl_xor_sync(0xffffffffu, l_lo, 1);
    l_lo += __shfl_xor_sync(0xffffffffu, l_lo, 2);
    l_hi += __shfl_xor_sync(0xffffffffu, l_hi, 1);
    l_hi += __shfl_xor_sync(0xffffffffu, l_hi, 2);
    const float inv_lo = 1.f / l_lo;
    const float inv_hi = 1.f / l_hi;

    const int row_lo = qb + w * 16 + g;
    float* ylo = Y + (size_t)(b * SEQ + row_lo) * EMB + h * HDIM;
    float* yhi = ylo + 8 * EMB;
    #pragma unroll
    for (int nt = 0; nt < 8; nt++) {
        const int col = nt * 8 + 2 * tig;
        float2 v0 = { o[nt][0] * inv_lo, o[nt][1] * inv_lo };
        float2 v1 = { o[nt][2] * inv_hi, o[nt][3] * inv_hi };
        *(float2*)(ylo + col) = v0;
        *(float2*)(yhi + col) = v1;
    }
}

// ===========================================================================
// kernel_launch
// ===========================================================================
extern "C" void kernel_launch(void* const* d_in, const int* in_sizes, int n_in,
                              void* d_out, int out_size)
{
    const float* x      = (const float*)d_in[0];
    const float* W_attn = (const float*)d_in[1];
    const float* b_attn = (const float*)d_in[2];
    const float* W_proj = (const float*)d_in[3];
    const float* b_proj = (const float*)d_in[4];
    float* out = (float*)d_out;

    float *qkv, *y, *wt_attn, *wt_proj;
    cudaGetSymbolAddress((void**)&qkv, g_qkv);
    cudaGetSymbolAddress((void**)&y, g_y);
    cudaGetSymbolAddress((void**)&wt_attn, g_wt_attn);
    cudaGetSymbolAddress((void**)&wt_proj, g_wt_proj);

    static bool attr_set = false;
    if (!attr_set) {
        cudaFuncSetAttribute(flash_mma, cudaFuncAttributeMaxDynamicSharedMemorySize,
                             FLASH_SMEM_BYTES);
        cudaFuncSetAttribute(gemm_mma, cudaFuncAttributeMaxDynamicSharedMemorySize,
                             GEMM_SMEM_BYTES);
        attr_set = true;
    }

    // 0) transpose weights to K-major (N, K), tf32-rounded
    {
        dim3 bdim(32, 8);
        transpose_k<<<dim3(QKV_N / 32, EMB / 32), bdim>>>(W_attn, wt_attn, EMB, QKV_N);
        transpose_k<<<dim3(EMB / 32, EMB / 32), bdim>>>(W_proj, wt_proj, EMB, EMB);
    }

    // 1) QKV projection (mma.sync tf32, cp.async pipeline)
    {
        dim3 grid(QKV_N / BN, M_ROWS / BM);
        gemm_mma<<<grid, 256, GEMM_SMEM_BYTES>>>(x, wt_attn, b_attn, qkv, QKV_N, EMB);
    }

    // 2) causal flash attention (mma.sync tf32, 2xTF32 QK, cp.async K/V, 3 CTA/SM)
    {
        dim3 grid(SEQ / QT, NHEAD, BATCH);
        flash_mma<<<grid, 128, FLASH_SMEM_BYTES>>>(qkv, y);
    }

    // 3) output projection (mma.sync tf32, cp.async pipeline)
    {
        dim3 grid(EMB / BN, M_ROWS / BM);
        gemm_mma<<<grid, 256, GEMM_SMEM_BYTES>>>(y, wt_proj, b_proj, out, EMB, EMB);
    }
}

// round 14
// speedup vs baseline: 1.1511x; 1.0361x over previous
#include <cuda_runtime.h>
#include <cuda_bf16.h>
#include <cstdint>

// Problem constants
#define BATCH 4
#define SEQ   2048
#define EMB   1024
#define NHEAD 16
#define HDIM  64
#define M_ROWS (BATCH * SEQ)      // 8192
#define QKV_N  (3 * EMB)          // 3072

// Scratch (device globals: no allocation allowed)
__device__ float g_qkv[(size_t)M_ROWS * QKV_N];   // (B*T, 3C); cols>=EMB tf32-rounded
__device__ float g_y[(size_t)M_ROWS * EMB];       // (B*T, C)
__device__ float g_wt_attn[(size_t)QKV_N * EMB];  // W_attn^T (3072,1024), tf32-rounded
__device__ float g_wt_proj[(size_t)EMB * EMB];    // W_proj^T (1024,1024), tf32-rounded

__device__ __forceinline__ uint32_t f2tf32(float f) {
    uint32_t r;
    asm("cvt.rna.tf32.f32 %0, %1;" : "=r"(r) : "f"(f));
    return r;
}

__device__ __forceinline__ void mma_tf32(float* c, const uint32_t* a, const uint32_t* b) {
    asm volatile(
        "mma.sync.aligned.m16n8k8.row.col.f32.tf32.tf32.f32 "
        "{%0,%1,%2,%3}, {%4,%5,%6,%7}, {%8,%9}, {%0,%1,%2,%3};"
        : "+f"(c[0]), "+f"(c[1]), "+f"(c[2]), "+f"(c[3])
        : "r"(a[0]), "r"(a[1]), "r"(a[2]), "r"(a[3]), "r"(b[0]), "r"(b[1]));
}

__device__ __forceinline__ void cpa16(void* dst_smem, const void* src) {
    uint32_t d = (uint32_t)__cvta_generic_to_shared(dst_smem);
    asm volatile("cp.async.cg.shared.global [%0], [%1], 16;" :: "r"(d), "l"(src) : "memory");
}
#define CP_COMMIT() asm volatile("cp.async.commit_group;" ::: "memory")
#define CP_WAIT2()  asm volatile("cp.async.wait_group 2;" ::: "memory")
#define CP_WAIT1()  asm volatile("cp.async.wait_group 1;" ::: "memory")
#define CP_WAIT0()  asm volatile("cp.async.wait_group 0;" ::: "memory")

// ===========================================================================
// mma.sync tf32 GEMM with 4-stage cp.async pipeline.
// NEW: columns >= round_from_col are rna-rounded to tf32 at the epilogue
// (bias add first, then round — identical op order to flash's old frag-load
// rounding, so downstream flash math is bit-identical).
// ===========================================================================
#define BM 128
#define BN 128
#define BKT 16
#define ASTR 20
#define NST 4

#define GEMM_AS_FLOATS (BM * ASTR)
#define GEMM_BS_FLOATS (BN * ASTR)
#define GEMM_SMEM_FLOATS (NST * (GEMM_AS_FLOATS + GEMM_BS_FLOATS))
#define GEMM_SMEM_BYTES  (GEMM_SMEM_FLOATS * 4)

__global__ __launch_bounds__(256, 2) void gemm_mma(
    const float* __restrict__ A, const float* __restrict__ Bt,
    const float* __restrict__ bias, float* __restrict__ C,
    int N, int K, int round_from_col)
{
    extern __shared__ __align__(16) float gsm[];
    float* Asm = gsm;
    float* Bsm = gsm + NST * GEMM_AS_FLOATS;

    const int tid  = threadIdx.x;
    const int warp = tid >> 5;
    const int lane = tid & 31;
    const int wm = warp >> 1;
    const int wn = warp & 1;
    const int g   = lane >> 2;
    const int tig = lane & 3;
    const int m0 = blockIdx.y * BM;
    const int n0 = blockIdx.x * BN;

    const int ch0 = tid * 2;
    const int lr0 = ch0 >> 2;
    const int lk0 = (ch0 & 3) * 4;
    const int lr1 = (ch0 + 1) >> 2;
    const int lk1 = ((ch0 + 1) & 3) * 4;

    const float* Abase = A  + (size_t)m0 * K;
    const float* Bbase = Bt + (size_t)n0 * K;

    float acc[2][8][4];
    #pragma unroll
    for (int i = 0; i < 2; i++)
        #pragma unroll
        for (int j = 0; j < 8; j++)
            #pragma unroll
            for (int r = 0; r < 4; r++) acc[i][j][r] = 0.f;

    const int niter = K / BKT;

    #pragma unroll
    for (int s = 0; s < NST - 1; s++) {
        const int k0 = s * BKT;
        cpa16(&Asm[s * GEMM_AS_FLOATS + lr0 * ASTR + lk0], Abase + (size_t)lr0 * K + k0 + lk0);
        cpa16(&Asm[s * GEMM_AS_FLOATS + lr1 * ASTR + lk1], Abase + (size_t)lr1 * K + k0 + lk1);
        cpa16(&Bsm[s * GEMM_BS_FLOATS + lr0 * ASTR + lk0], Bbase + (size_t)lr0 * K + k0 + lk0);
        cpa16(&Bsm[s * GEMM_BS_FLOATS + lr1 * ASTR + lk1], Bbase + (size_t)lr1 * K + k0 + lk1);
        CP_COMMIT();
    }

    for (int it = 0; it < niter; it++) {
        const int st = it & (NST - 1);
        const float* As = Asm + st * GEMM_AS_FLOATS;
        const float* Bs = Bsm + st * GEMM_BS_FLOATS;

        CP_WAIT2();
        __syncthreads();

        const int pre = it + NST - 1;
        if (pre < niter) {
            const int ps = pre & (NST - 1);
            const int k0 = pre * BKT;
            cpa16(&Asm[ps * GEMM_AS_FLOATS + lr0 * ASTR + lk0], Abase + (size_t)lr0 * K + k0 + lk0);
            cpa16(&Asm[ps * GEMM_AS_FLOATS + lr1 * ASTR + lk1], Abase + (size_t)lr1 * K + k0 + lk1);
            cpa16(&Bsm[ps * GEMM_BS_FLOATS + lr0 * ASTR + lk0], Bbase + (size_t)lr0 * K + k0 + lk0);
            cpa16(&Bsm[ps * GEMM_BS_FLOATS + lr1 * ASTR + lk1], Bbase + (size_t)lr1 * K + k0 + lk1);
        }
        CP_COMMIT();

        #pragma unroll
        for (int ks = 0; ks < 2; ks++) {
            const int kb = ks * 8;
            uint32_t af[2][4], bf[8][2];
            #pragma unroll
            for (int mf = 0; mf < 2; mf++) {
                const int base = (wm * 32 + mf * 16 + g) * ASTR + kb + tig;
                af[mf][0] = f2tf32(As[base]);
                af[mf][1] = f2tf32(As[base + 8 * ASTR]);
                af[mf][2] = f2tf32(As[base + 4]);
                af[mf][3] = f2tf32(As[base + 8 * ASTR + 4]);
            }
            #pragma unroll
            for (int nf = 0; nf < 8; nf++) {
                const int base = (wn * 64 + nf * 8 + g) * ASTR + kb + tig;
                bf[nf][0] = __float_as_uint(Bs[base]);
                bf[nf][1] = __float_as_uint(Bs[base + 4]);
            }
            #pragma unroll
            for (int mf = 0; mf < 2; mf++)
                #pragma unroll
                for (int nf = 0; nf < 8; nf++)
                    mma_tf32(acc[mf][nf], af[mf], bf[nf]);
        }
    }

    #pragma unroll
    for (int mf = 0; mf < 2; mf++) {
        const int row = m0 + wm * 32 + mf * 16 + g;
        #pragma unroll
        for (int nf = 0; nf < 8; nf++) {
            const int col = n0 + wn * 64 + nf * 8 + tig * 2;
            const float b0 = __ldg(bias + col);
            const float b1 = __ldg(bias + col + 1);
            float2 v0 = { acc[mf][nf][0] + b0, acc[mf][nf][1] + b1 };
            float2 v1 = { acc[mf][nf][2] + b0, acc[mf][nf][3] + b1 };
            if (col >= round_from_col) {   // K/V region: pre-round to tf32 for flash
                v0.x = __uint_as_float(f2tf32(v0.x));
                v0.y = __uint_as_float(f2tf32(v0.y));
                v1.x = __uint_as_float(f2tf32(v1.x));
                v1.y = __uint_as_float(f2tf32(v1.y));
            }
            *(float2*)(C + (size_t)row * N + col)       = v0;
            *(float2*)(C + (size_t)(row + 8) * N + col) = v1;
        }
    }
}

// ===========================================================================
// transpose + tf32 round (unchanged)
// ===========================================================================
__global__ __launch_bounds__(256) void transpose_k(
    const float* __restrict__ in, float* __restrict__ out, int R, int C)
{
    __shared__ float t[32][33];
    const int bx = blockIdx.x * 32;
    const int by = blockIdx.y * 32;
    #pragma unroll
    for (int j = 0; j < 32; j += 8) {
        int r = by + threadIdx.y + j;
        t[threadIdx.y + j][threadIdx.x] = in[(size_t)r * C + bx + threadIdx.x];
    }
    __syncthreads();
    #pragma unroll
    for (int j = 0; j < 32; j += 8) {
        int c = bx + threadIdx.y + j;
        out[(size_t)c * R + by + threadIdx.x] =
            __uint_as_float(f2tf32(t[threadIdx.x][threadIdx.y + j]));
    }
}

// ===========================================================================
// Tensor-core flash attention v4 (causal), mma.sync tf32.
// vs R13: K and V arrive pre-rounded to tf32 (GEMM epilogue), so fragment
// loads are raw LDS — no cvt in the hot loop. Q path unchanged (exact split).
// Bit-identical numerics to v3.
// ===========================================================================
#define QT 64
#define KT 64
#define KSTR 68
#define VSTR 72
#define PSTR 68

// smem layout (floats): raw K (2 stages), raw V (1 stage), P
#define S_K0  0
#define S_K1  (S_K0 + KT * KSTR)                 // 4352
#define S_V   (S_K1 + KT * KSTR)                 // 8704
#define S_P   (S_V + KT * VSTR)                  // 13312
#define FLASH_SMEM_FLOATS (S_P + 4 * 16 * PSTR)  // 17664
#define FLASH_SMEM_BYTES  (FLASH_SMEM_FLOATS * 4) // 70656

__global__ __launch_bounds__(128, 3) void flash_mma(
    const float* __restrict__ qkv, float* __restrict__ Y)
{
    extern __shared__ __align__(16) float sm[];
    uint32_t* smu = (uint32_t*)sm;

    const int b  = blockIdx.z;
    const int h  = blockIdx.y;
    const int qt = gridDim.x - 1 - blockIdx.x;   // heavy blocks first
    const int qb = qt * QT;
    const int tid  = threadIdx.x;
    const int w    = tid >> 5;
    const int lane = tid & 31;
    const int g    = lane >> 2;
    const int tig  = lane & 3;

    const float* base = qkv + (size_t)b * SEQ * QKV_N;

    // loader mapping for cp.async: 8 chunks of 16B per thread per tile
    const int lrow = tid >> 4;            // 0..7  (row group base)
    const int lcol = (tid & 15) * 4;      // 0..60 (float offset)

    auto issue_K = [&](int k0, int st) {
        float* Ks = sm + (st ? S_K1 : S_K0);
        #pragma unroll
        for (int i = 0; i < 8; i++) {
            const int r = lrow + i * 8;
            cpa16(&Ks[r * KSTR + lcol],
                  base + (size_t)(k0 + r) * QKV_N + EMB + h * HDIM + lcol);
        }
        CP_COMMIT();
    };
    auto issue_V = [&](int k0) {
        float* Vs = sm + S_V;
        #pragma unroll
        for (int i = 0; i < 8; i++) {
            const int r = lrow + i * 8;
            cpa16(&Vs[r * VSTR + lcol],
                  base + (size_t)(k0 + r) * QKV_N + 2 * EMB + h * HDIM + lcol);
        }
        CP_COMMIT();
    };

    // ---- Q fragments (scaled by 1/8 exactly, split hi/lo; split is exact) ----
    uint32_t qhi[8][4], qlo[8][4];
    {
        const float* qlorow = base + (size_t)(qb + w * 16 + g) * QKV_N + h * HDIM;
        const float* qhirow = qlorow + 8 * QKV_N;
        #pragma unroll
        for (int kk = 0; kk < 8; kk++) {
            float v0 = qlorow[kk * 8 + tig]     * 0.125f;
            float v1 = qhirow[kk * 8 + tig]     * 0.125f;
            float v2 = qlorow[kk * 8 + tig + 4] * 0.125f;
            float v3 = qhirow[kk * 8 + tig + 4] * 0.125f;
            float h0 = __uint_as_float(__float_as_uint(v0) & 0xffffe000u);
            float h1 = __uint_as_float(__float_as_uint(v1) & 0xffffe000u);
            float h2 = __uint_as_float(__float_as_uint(v2) & 0xffffe000u);
            float h3 = __uint_as_float(__float_as_uint(v3) & 0xffffe000u);
            qhi[kk][0] = __float_as_uint(h0);
            qhi[kk][1] = __float_as_uint(h1);
            qhi[kk][2] = __float_as_uint(h2);
            qhi[kk][3] = __float_as_uint(h3);
            qlo[kk][0] = f2tf32(v0 - h0);
            qlo[kk][1] = f2tf32(v1 - h1);
            qlo[kk][2] = f2tf32(v2 - h2);
            qlo[kk][3] = f2tf32(v3 - h3);
        }
    }

    // prologue: K(0) into stage 0
    issue_K(0, 0);

    float o[8][4];
    #pragma unroll
    for (int nt = 0; nt < 8; nt++)
        #pragma unroll
        for (int r = 0; r < 4; r++) o[nt][r] = 0.f;
    float m_lo = -1e30f, m_hi = -1e30f;
    float l_lo = 0.f,    l_hi = 0.f;

    uint32_t* Pw = smu + S_P + w * 16 * PSTR;

    for (int kt = 0; kt <= qt; kt++) {
        const int st = kt & 1;
        const uint32_t* Ks = smu + (st ? S_K1 : S_K0);
        const uint32_t* Vs = smu + S_V;

        // issue V(kt), then K(kt+1); wait so that K(kt) and V(kt) are complete
        issue_V(kt * KT);
        if (kt < qt) {
            issue_K((kt + 1) * KT, st ^ 1);
            CP_WAIT1();
        } else {
            CP_WAIT0();
        }
        __syncthreads();

        // ---- S = Q.K^T (2xTF32: exact-Q x pre-rounded K, raw LDS) ----
        float s[8][4];
        #pragma unroll
        for (int nt = 0; nt < 8; nt++)
            #pragma unroll
            for (int r = 0; r < 4; r++) s[nt][r] = 0.f;

        #pragma unroll
        for (int kk = 0; kk < 8; kk++) {
            #pragma unroll
            for (int nt = 0; nt < 8; nt++) {
                const int ra = nt * 8 + g;
                uint32_t kr[2];
                kr[0] = Ks[ra * KSTR + kk * 8 + tig];       // already tf32 bits
                kr[1] = Ks[ra * KSTR + kk * 8 + tig + 4];
                mma_tf32(s[nt], qhi[kk], kr);
                mma_tf32(s[nt], qlo[kk], kr);
            }
        }

        // ---- causal mask (diagonal tile only) ----
        if (kt == qt) {
            const int rlo = w * 16 + g;
            const int rhi = rlo + 8;
            #pragma unroll
            for (int nt = 0; nt < 8; nt++) {
                const int c0 = nt * 8 + 2 * tig;
                if (c0     > rlo) s[nt][0] = -1e30f;
                if (c0 + 1 > rlo) s[nt][1] = -1e30f;
                if (c0     > rhi) s[nt][2] = -1e30f;
                if (c0 + 1 > rhi) s[nt][3] = -1e30f;
            }
        }

        // ---- online softmax ----
        float mx_lo = -1e30f, mx_hi = -1e30f;
        #pragma unroll
        for (int nt = 0; nt < 8; nt++) {
            mx_lo = fmaxf(mx_lo, fmaxf(s[nt][0], s[nt][1]));
            mx_hi = fmaxf(mx_hi, fmaxf(s[nt][2], s[nt][3]));
        }
        mx_lo = fmaxf(mx_lo, __shfl_xor_sync(0xffffffffu, mx_lo, 1));
        mx_lo = fmaxf(mx_lo, __shfl_xor_sync(0xffffffffu, mx_lo, 2));
        mx_hi = fmaxf(mx_hi, __shfl_xor_sync(0xffffffffu, mx_hi, 1));
        mx_hi = fmaxf(mx_hi, __shfl_xor_sync(0xffffffffu, mx_hi, 2));

        const float mn_lo = fmaxf(m_lo, mx_lo);
        const float mn_hi = fmaxf(m_hi, mx_hi);
        const float cr_lo = __expf(m_lo - mn_lo);
        const float cr_hi = __expf(m_hi - mn_hi);
        m_lo = mn_lo; m_hi = mn_hi;
        l_lo *= cr_lo; l_hi *= cr_hi;
        #pragma unroll
        for (int nt = 0; nt < 8; nt++) {
            o[nt][0] *= cr_lo;
            o[nt][1] *= cr_lo;
            o[nt][2] *= cr_hi;
            o[nt][3] *= cr_hi;
        }

        // ---- P = exp(s - m), accumulate l, stage P to smem ----
        #pragma unroll
        for (int nt = 0; nt < 8; nt++) {
            float p0 = __expf(s[nt][0] - mn_lo);
            float p1 = __expf(s[nt][1] - mn_lo);
            float p2 = __expf(s[nt][2] - mn_hi);
            float p3 = __expf(s[nt][3] - mn_hi);
            l_lo += p0 + p1;
            l_hi += p2 + p3;
            uint32_t* Plo = Pw + g * PSTR + nt * 8 + 2 * tig;
            uint32_t* Phi = Pw + (g + 8) * PSTR + nt * 8 + 2 * tig;
            Plo[0] = f2tf32(p0);
            Plo[1] = f2tf32(p1);
            Phi[0] = f2tf32(p2);
            Phi[1] = f2tf32(p3);
        }
        __syncwarp();

        // ---- O += P.V (V pre-rounded, raw LDS) ----
        #pragma unroll
        for (int kk = 0; kk < 8; kk++) {
            uint32_t pa[4];
            pa[0] = Pw[g * PSTR + kk * 8 + tig];
            pa[1] = Pw[(g + 8) * PSTR + kk * 8 + tig];
            pa[2] = Pw[g * PSTR + kk * 8 + tig + 4];
            pa[3] = Pw[(g + 8) * PSTR + kk * 8 + tig + 4];
            #pragma unroll
            for (int nt = 0; nt < 8; nt++) {
                uint32_t vb[2];
                vb[0] = Vs[(kk * 8 + tig) * VSTR + nt * 8 + g];       // already tf32
                vb[1] = Vs[(kk * 8 + tig + 4) * VSTR + nt * 8 + g];
                mma_tf32(o[nt], pa, vb);
            }
        }
        __syncthreads();   // all reads of V and K stage st done before reuse
    }

    // ---- finalize: full row sums, normalize, write ----
    l_lo += __shfl_xor_sync(0xffffffffu, l_lo, 1);
    l_lo += __shfl_xor_sync(0xffffffffu, l_lo, 2);
    l_hi += __shfl_xor_sync(0xffffffffu, l_hi, 1);
    l_hi += __shfl_xor_sync(0xffffffffu, l_hi, 2);
    const float inv_lo = 1.f / l_lo;
    const float inv_hi = 1.f / l_hi;

    const int row_lo = qb + w * 16 + g;
    float* ylo = Y + (size_t)(b * SEQ + row_lo) * EMB + h * HDIM;
    float* yhi = ylo + 8 * EMB;
    #pragma unroll
    for (int nt = 0; nt < 8; nt++) {
        const int col = nt * 8 + 2 * tig;
        float2 v0 = { o[nt][0] * inv_lo, o[nt][1] * inv_lo };
        float2 v1 = { o[nt][2] * inv_hi, o[nt][3] * inv_hi };
        *(float2*)(ylo + col) = v0;
        *(float2*)(yhi + col) = v1;
    }
}

// ===========================================================================
// kernel_launch
// ===========================================================================
extern "C" void kernel_launch(void* const* d_in, const int* in_sizes, int n_in,
                              void* d_out, int out_size)
{
    const float* x      = (const float*)d_in[0];
    const float* W_attn = (const float*)d_in[1];
    const float* b_attn = (const float*)d_in[2];
    const float* W_proj = (const float*)d_in[3];
    const float* b_proj = (const float*)d_in[4];
    float* out = (float*)d_out;

    float *qkv, *y, *wt_attn, *wt_proj;
    cudaGetSymbolAddress((void**)&qkv, g_qkv);
    cudaGetSymbolAddress((void**)&y, g_y);
    cudaGetSymbolAddress((void**)&wt_attn, g_wt_attn);
    cudaGetSymbolAddress((void**)&wt_proj, g_wt_proj);

    static bool attr_set = false;
    if (!attr_set) {
        cudaFuncSetAttribute(flash_mma, cudaFuncAttributeMaxDynamicSharedMemorySize,
                             FLASH_SMEM_BYTES);
        cudaFuncSetAttribute(gemm_mma, cudaFuncAttributeMaxDynamicSharedMemorySize,
                             GEMM_SMEM_BYTES);
        attr_set = true;
    }

    // 0) transpose weights to K-major (N, K), tf32-rounded
    {
        dim3 bdim(32, 8);
        transpose_k<<<dim3(QKV_N / 32, EMB / 32), bdim>>>(W_attn, wt_attn, EMB, QKV_N);
        transpose_k<<<dim3(EMB / 32, EMB / 32), bdim>>>(W_proj, wt_proj, EMB, EMB);
    }

    // 1) QKV projection; K/V columns (>= EMB) pre-rounded to tf32 for flash
    {
        dim3 grid(QKV_N / BN, M_ROWS / BM);
        gemm_mma<<<grid, 256, GEMM_SMEM_BYTES>>>(x, wt_attn, b_attn, qkv,
                                                 QKV_N, EMB, EMB);
    }

    // 2) causal flash attention (2xTF32 QK, raw-LDS K/V fragments, 3 CTA/SM)
    {
        dim3 grid(SEQ / QT, NHEAD, BATCH);
        flash_mma<<<grid, 128, FLASH_SMEM_BYTES>>>(qkv, y);
    }

    // 3) output projection (no rounding — final output)
    {
        dim3 grid(EMB / BN, M_ROWS / BM);
        gemm_mma<<<grid, 256, GEMM_SMEM_BYTES>>>(y, wt_proj, b_proj, out,
                                                 EMB, EMB, 0x7fffffff);
    }
}